// round 7
// baseline (speedup 1.0000x reference)
#include <cuda_runtime.h>
#include <math.h>

// ---------------- problem dims ----------------
// N=64, L=2048, C1=64, C2=128, C3=256, LAT=512, LD=64
// out: [64, 1, 8191] float32

// ---------------- device scratch ----------------
__device__ float g_h1[64 * 64 * 2048];     // encoder stage 1
__device__ float g_h2[64 * 128 * 2048];    // encoder stage 2
__device__ float g_h3[64 * 256 * 2048];    // encoder stage 3
__device__ float g_cmu[64 * 512];          // class_mu (== class_logvar)
__device__ float g_smu[64 * 512];          // style_mu
__device__ float g_slv[64 * 512];          // style_logvar
__device__ float g_zc[512];
__device__ float g_zs[64 * 512];
__device__ float g_content[256 * 64];      // 16384
__device__ float g_d1[128 * 64];
__device__ float g_source[64 * 64];        // 4096
__device__ float g_m[64 * 256 * 64];       // 64 x 16384
__device__ float g_md1[64 * 128 * 64];
__device__ float g_md2[64 * 64 * 64];      // 64 x 4096

// ---------------- generic 1D conv (k=3, same padding) ----------------
// template: CIN channels in, CICH = ci chunk staged in smem,
// LPT = outputs along L per thread, ACT: 0 = LeakyReLU(0.01), 1 = ReLU
// Block = 256 threads. LANES=16 threads over L, 16 thread-groups x COPT=4 co.
template <int CIN, int CICH, int LPT, int ACT>
__global__ void __launch_bounds__(256) conv3k(
    const float* __restrict__ x, const float* __restrict__ W,
    const float* __restrict__ bias, float* __restrict__ y,
    int L, int Cout)
{
    constexpr int LANES = 16;
    constexpr int COPT  = 4;
    constexpr int LT    = LANES * LPT;            // L tile
    constexpr int COT   = (256 / LANES) * COPT;   // 64 output channels / block
    constexpr int ROW   = ((LT + 2 + 3) / 4) * 4; // padded row (16B aligned)

    __shared__ __align__(16) float xs[CICH][ROW];
    __shared__ float ws[CICH][COT][3];

    const int n  = blockIdx.z;
    const int cb = blockIdx.y * COT;
    const int l0 = blockIdx.x * LT;
    const int tid = threadIdx.x;
    const int tl  = tid & (LANES - 1);
    const int tc  = tid / LANES;

    float acc[COPT][LPT];
#pragma unroll
    for (int c = 0; c < COPT; ++c)
#pragma unroll
        for (int p = 0; p < LPT; ++p) acc[c][p] = 0.f;

    const float* xn = x + n * CIN * L;

    for (int c0 = 0; c0 < CIN; c0 += CICH) {
        __syncthreads();
        // stage input tile (with halo) into smem
        for (int idx = tid; idx < CICH * (LT + 2); idx += 256) {
            int ci = idx / (LT + 2);
            int p  = idx - ci * (LT + 2);
            int gl = l0 + p - 1;
            xs[ci][p] = (gl >= 0 && gl < L) ? xn[(c0 + ci) * L + gl] : 0.f;
        }
        // stage weights as ws[ci][co][k]
        for (int idx = tid; idx < CICH * COT * 3; idx += 256) {
            int co = idx / (CICH * 3);
            int r  = idx - co * (CICH * 3);
            int ci = r / 3, k = r - ci * 3;
            ws[ci][co][k] = W[(cb + co) * (CIN * 3) + (c0 + ci) * 3 + k];
        }
        __syncthreads();

#pragma unroll
        for (int ci = 0; ci < CICH; ++ci) {
            float xv[LPT + 2];
            const int xb = tl * LPT;
            if constexpr (LPT == 8) {
                float4 v0 = *reinterpret_cast<const float4*>(&xs[ci][xb]);
                float4 v1 = *reinterpret_cast<const float4*>(&xs[ci][xb + 4]);
                float2 v2 = *reinterpret_cast<const float2*>(&xs[ci][xb + 8]);
                xv[0] = v0.x; xv[1] = v0.y; xv[2] = v0.z; xv[3] = v0.w;
                xv[4] = v1.x; xv[5] = v1.y; xv[6] = v1.z; xv[7] = v1.w;
                xv[8] = v2.x; xv[9] = v2.y;
            } else {
                float4 v0 = *reinterpret_cast<const float4*>(&xs[ci][xb]);
                float2 v2 = *reinterpret_cast<const float2*>(&xs[ci][xb + 4]);
                xv[0] = v0.x; xv[1] = v0.y; xv[2] = v0.z; xv[3] = v0.w;
                xv[4] = v2.x; xv[5] = v2.y;
            }
#pragma unroll
            for (int cc = 0; cc < COPT; ++cc) {
                const int co = tc * COPT + cc;
                const float w0 = ws[ci][co][0];
                const float w1 = ws[ci][co][1];
                const float w2 = ws[ci][co][2];
#pragma unroll
                for (int p = 0; p < LPT; ++p)
                    acc[cc][p] += w0 * xv[p] + w1 * xv[p + 1] + w2 * xv[p + 2];
            }
        }
    }

    // epilogue: bias + activation, vectorized stores
#pragma unroll
    for (int cc = 0; cc < COPT; ++cc) {
        const int co = cb + tc * COPT + cc;
        const float bv = bias[co];
        float o[LPT];
#pragma unroll
        for (int p = 0; p < LPT; ++p) {
            float v = acc[cc][p] + bv;
            o[p] = (ACT == 0) ? (v > 0.f ? v : 0.01f * v)
                              : (v > 0.f ? v : 0.f);
        }
        float* yp = y + (n * Cout + co) * L + l0 + tl * LPT;
#pragma unroll
        for (int p = 0; p < LPT; p += 4)
            *reinterpret_cast<float4*>(yp + p) =
                make_float4(o[p], o[p + 1], o[p + 2], o[p + 3]);
    }
}

// ---------------- heads: 6 dots of length 2048 per (n, c) ----------------
__global__ void __launch_bounds__(256) heads_k(
    const float* __restrict__ h3,
    const float* __restrict__ cmW, const float* __restrict__ cmb,
    const float* __restrict__ smW, const float* __restrict__ smb,
    const float* __restrict__ slW, const float* __restrict__ slb,
    float* __restrict__ cmu, float* __restrict__ smu, float* __restrict__ slv)
{
    const int c = blockIdx.x, n = blockIdx.y;
    const float4* h  = reinterpret_cast<const float4*>(h3 + (n * 256 + c) * 2048);
    const float4* w0 = reinterpret_cast<const float4*>(cmW);
    const float4* w1 = reinterpret_cast<const float4*>(cmW + 2048);
    const float4* w2 = reinterpret_cast<const float4*>(smW);
    const float4* w3 = reinterpret_cast<const float4*>(smW + 2048);
    const float4* w4 = reinterpret_cast<const float4*>(slW);
    const float4* w5 = reinterpret_cast<const float4*>(slW + 2048);

    float a0 = 0, a1 = 0, a2 = 0, a3 = 0, a4 = 0, a5 = 0;
    for (int i = threadIdx.x; i < 512; i += 256) {
        float4 hv = h[i];
        float4 t;
        t = w0[i]; a0 += hv.x * t.x + hv.y * t.y + hv.z * t.z + hv.w * t.w;
        t = w1[i]; a1 += hv.x * t.x + hv.y * t.y + hv.z * t.z + hv.w * t.w;
        t = w2[i]; a2 += hv.x * t.x + hv.y * t.y + hv.z * t.z + hv.w * t.w;
        t = w3[i]; a3 += hv.x * t.x + hv.y * t.y + hv.z * t.z + hv.w * t.w;
        t = w4[i]; a4 += hv.x * t.x + hv.y * t.y + hv.z * t.z + hv.w * t.w;
        t = w5[i]; a5 += hv.x * t.x + hv.y * t.y + hv.z * t.z + hv.w * t.w;
    }
#pragma unroll
    for (int o = 16; o; o >>= 1) {
        a0 += __shfl_xor_sync(0xffffffffu, a0, o);
        a1 += __shfl_xor_sync(0xffffffffu, a1, o);
        a2 += __shfl_xor_sync(0xffffffffu, a2, o);
        a3 += __shfl_xor_sync(0xffffffffu, a3, o);
        a4 += __shfl_xor_sync(0xffffffffu, a4, o);
        a5 += __shfl_xor_sync(0xffffffffu, a5, o);
    }
    __shared__ float red[6][8];
    const int lane = threadIdx.x & 31, warp = threadIdx.x >> 5;
    if (lane == 0) {
        red[0][warp] = a0; red[1][warp] = a1; red[2][warp] = a2;
        red[3][warp] = a3; red[4][warp] = a4; red[5][warp] = a5;
    }
    __syncthreads();
    if (threadIdx.x < 6) {
        float s = 0.f;
#pragma unroll
        for (int w = 0; w < 8; ++w) s += red[threadIdx.x][w];
        const int d = threadIdx.x & 1;
        const int which = threadIdx.x >> 1;
        const int outi = n * 512 + c * 2 + d;
        if (which == 0)      cmu[outi] = s + cmb[d];
        else if (which == 1) smu[outi] = s + smb[d];
        else                 slv[outi] = s + slb[d];
    }
}

// ---------------- group evidence fusion + z_c ----------------
__global__ void fuse_zc_k(const float* __restrict__ cmu,
                          const float* __restrict__ eps_c,
                          float* __restrict__ zc)
{
    const int j = threadIdx.x; // 512 threads
    float ps = 0.f, ms = 0.f;
#pragma unroll 8
    for (int n = 0; n < 64; ++n) {
        float cm = cmu[n * 512 + j];
        float p = expf(-cm);   // prec = exp(-class_logvar), class_logvar == class_mu
        ps += p;
        ms += cm * p;
    }
    const float gv = 1.f / ps;              // group_var
    zc[j] = eps_c[j] * sqrtf(gv) + gv * ms; // eps*exp(0.5*log(gv)) + group_mu
}

// ---------------- z_s ----------------
__global__ void zs_k(const float* __restrict__ smu, const float* __restrict__ slv,
                     const float* __restrict__ eps_s, float* __restrict__ zs)
{
    const int i = blockIdx.x * 256 + threadIdx.x;
    if (i < 64 * 512) zs[i] = eps_s[i] * expf(0.5f * slv[i]) + smu[i];
}

// ---------------- matvec: content = pc_W @ z_c + pc_b ----------------
__global__ void __launch_bounds__(256) matvec_k(
    const float* __restrict__ Wm, const float* __restrict__ bv,
    const float* __restrict__ z, float* __restrict__ out, int rows)
{
    const int gw = (blockIdx.x * 256 + threadIdx.x) >> 5;
    const int lane = threadIdx.x & 31;
    if (gw >= rows) return;
    const float4* row = reinterpret_cast<const float4*>(Wm + gw * 512);
    const float4* z4  = reinterpret_cast<const float4*>(z);
    float acc = 0.f;
#pragma unroll
    for (int j = lane; j < 128; j += 32) {
        float4 a = row[j], b = z4[j];
        acc += a.x * b.x + a.y * b.y + a.z * b.z + a.w * b.w;
    }
#pragma unroll
    for (int o = 16; o; o >>= 1) acc += __shfl_xor_sync(0xffffffffu, acc, o);
    if (lane == 0) out[gw] = acc + bv[gw];
}

// ---------------- GEMM: m[n][i] = zs[n,:] . ps_W[i,:] + ps_b[i] ----------------
// block tile: 64 i-rows x all 64 n, j chunks of 16
__global__ void __launch_bounds__(256) gemm_m_k(
    const float* __restrict__ Wm, const float* __restrict__ bv,
    const float* __restrict__ zs, float* __restrict__ out)
{
    __shared__ __align__(16) float AsT[16][64]; // [j][i]
    __shared__ __align__(16) float Bs[16][68];  // [j][n], padded row
    const int i0  = blockIdx.x * 64;
    const int tid = threadIdx.x;
    const int tx  = tid & 15;   // i quad
    const int ty  = tid >> 4;   // n quad
    float acc[4][4];
#pragma unroll
    for (int q = 0; q < 4; ++q)
#pragma unroll
        for (int r = 0; r < 4; ++r) acc[q][r] = 0.f;

    for (int j0 = 0; j0 < 512; j0 += 16) {
        __syncthreads();
        {
            const int i  = tid >> 2;
            const int jj = (tid & 3) * 4;
            float4 a = *reinterpret_cast<const float4*>(Wm + (i0 + i) * 512 + j0 + jj);
            AsT[jj + 0][i] = a.x; AsT[jj + 1][i] = a.y;
            AsT[jj + 2][i] = a.z; AsT[jj + 3][i] = a.w;
        }
#pragma unroll
        for (int r = 0; r < 4; ++r) {
            const int idx = tid + r * 256;
            const int nn = idx >> 4, j = idx & 15;
            Bs[j][nn] = zs[nn * 512 + j0 + j];
        }
        __syncthreads();
#pragma unroll
        for (int j = 0; j < 16; ++j) {
            float4 av = *reinterpret_cast<const float4*>(&AsT[j][tx * 4]);
            float4 bb = *reinterpret_cast<const float4*>(&Bs[j][ty * 4]);
            float a4[4] = {av.x, av.y, av.z, av.w};
            float b4[4] = {bb.x, bb.y, bb.z, bb.w};
#pragma unroll
            for (int q = 0; q < 4; ++q)
#pragma unroll
                for (int r = 0; r < 4; ++r) acc[q][r] += a4[q] * b4[r];
        }
    }
    const float4 bias4 = *reinterpret_cast<const float4*>(&bv[i0 + tx * 4]);
#pragma unroll
    for (int r = 0; r < 4; ++r) {
        const int n = ty * 4 + r;
        float4 o;
        o.x = acc[0][r] + bias4.x;
        o.y = acc[1][r] + bias4.y;
        o.z = acc[2][r] + bias4.z;
        o.w = acc[3][r] + bias4.w;
        *reinterpret_cast<float4*>(&out[n * 16384 + i0 + tx * 4]) = o;
    }
}

// ---------------- final full convolution: out[n] = m2[n] (*) source ----------------
// block: (t-tile of 2048, n). Sliding register window over skewed source in smem.
__global__ void __launch_bounds__(256) fullconv_k(
    const float* __restrict__ m2, const float* __restrict__ src,
    float* __restrict__ out)
{
    __shared__ float ms[4096];
    __shared__ float sp[6336]; // skewed: phys = v + (v>>5), v in [0,6144)
    const int n  = blockIdx.y;
    const int t0 = blockIdx.x * 2048;
    const float* mn = m2 + n * 4096;
    for (int i = threadIdx.x; i < 4096; i += 256) ms[i] = mn[i];
    for (int v = threadIdx.x; v < 6144; v += 256) {
        const int u = v + t0 - 4096;
        sp[v + (v >> 5)] = (u >= 0 && u < 4096) ? src[u] : 0.f;
    }
    __syncthreads();

    const int tl  = threadIdx.x * 8;
    const int ilo = max(0, t0 - 4095);
    const int ihi = min(4096, t0 + 2048);
    float acc[8] = {0.f, 0.f, 0.f, 0.f, 0.f, 0.f, 0.f, 0.f};
    float r[8];
#pragma unroll
    for (int q = 0; q < 8; ++q) {
        const int v = tl + q + 4096 - ilo;
        r[q] = sp[v + (v >> 5)];
    }
#pragma unroll 8
    for (int i = ilo; i < ihi; ++i) {
        const float mv = ms[i];
#pragma unroll
        for (int q = 0; q < 8; ++q) acc[q] += mv * r[q];
#pragma unroll
        for (int q = 7; q > 0; --q) r[q] = r[q - 1];
        const int v = tl + 4095 - i;
        r[0] = sp[v + (v >> 5)];
    }
    const int tb = t0 + tl;
#pragma unroll
    for (int q = 0; q < 8; ++q) {
        const int t = tb + q;
        if (t < 8191) out[n * 8191 + t] = acc[q];
    }
}

// ---------------- launcher ----------------
extern "C" void kernel_launch(void* const* d_in, const int* in_sizes, int n_in,
                              void* d_out, int out_size)
{
    (void)in_sizes; (void)n_in; (void)out_size;
    const float* x    = (const float*)d_in[0];
    const float* W1   = (const float*)d_in[1];
    const float* b1   = (const float*)d_in[2];
    const float* W2   = (const float*)d_in[3];
    const float* b2   = (const float*)d_in[4];
    const float* W3   = (const float*)d_in[5];
    const float* b3   = (const float*)d_in[6];
    const float* cmW  = (const float*)d_in[7];
    const float* cmb  = (const float*)d_in[8];
    const float* smW  = (const float*)d_in[9];
    const float* smb  = (const float*)d_in[10];
    const float* slW  = (const float*)d_in[11];
    const float* slb  = (const float*)d_in[12];
    const float* pcW  = (const float*)d_in[13];
    const float* pcb  = (const float*)d_in[14];
    const float* psW  = (const float*)d_in[15];
    const float* psb  = (const float*)d_in[16];
    const float* V1   = (const float*)d_in[17];
    const float* c1   = (const float*)d_in[18];
    const float* V2   = (const float*)d_in[19];
    const float* c2   = (const float*)d_in[20];
    const float* epsc = (const float*)d_in[21];
    const float* epss = (const float*)d_in[22];
    float* out = (float*)d_out;

    void* p;
    cudaGetSymbolAddress(&p, g_h1);      float* h1      = (float*)p;
    cudaGetSymbolAddress(&p, g_h2);      float* h2      = (float*)p;
    cudaGetSymbolAddress(&p, g_h3);      float* h3      = (float*)p;
    cudaGetSymbolAddress(&p, g_cmu);     float* cmu     = (float*)p;
    cudaGetSymbolAddress(&p, g_smu);     float* smu     = (float*)p;
    cudaGetSymbolAddress(&p, g_slv);     float* slv     = (float*)p;
    cudaGetSymbolAddress(&p, g_zc);      float* zc      = (float*)p;
    cudaGetSymbolAddress(&p, g_zs);      float* zs      = (float*)p;
    cudaGetSymbolAddress(&p, g_content); float* content = (float*)p;
    cudaGetSymbolAddress(&p, g_d1);      float* d1      = (float*)p;
    cudaGetSymbolAddress(&p, g_source);  float* source  = (float*)p;
    cudaGetSymbolAddress(&p, g_m);       float* m       = (float*)p;
    cudaGetSymbolAddress(&p, g_md1);     float* md1     = (float*)p;
    cudaGetSymbolAddress(&p, g_md2);     float* md2     = (float*)p;

    // ---- encoder ----
    conv3k<1,   1, 8, 0><<<dim3(16, 1, 64), 256>>>(x,  W1, b1, h1, 2048, 64);
    conv3k<64, 16, 8, 0><<<dim3(16, 2, 64), 256>>>(h1, W2, b2, h2, 2048, 128);
    conv3k<128,16, 8, 0><<<dim3(16, 4, 64), 256>>>(h2, W3, b3, h3, 2048, 256);

    // ---- heads ----
    heads_k<<<dim3(256, 64), 256>>>(h3, cmW, cmb, smW, smb, slW, slb, cmu, smu, slv);

    // ---- latent ----
    fuse_zc_k<<<1, 512>>>(cmu, epsc, zc);
    zs_k<<<128, 256>>>(smu, slv, epss, zs);

    // ---- content path ----
    matvec_k<<<2048, 256>>>(pcW, pcb, zc, content, 16384);
    conv3k<256,16, 4, 1><<<dim3(1, 2, 1), 256>>>(content, V1, c1, d1, 64, 128);
    conv3k<128,16, 4, 1><<<dim3(1, 1, 1), 256>>>(d1, V2, c2, source, 64, 64);

    // ---- style path ----
    gemm_m_k<<<256, 256>>>(psW, psb, zs, m);
    conv3k<256,16, 4, 1><<<dim3(1, 2, 64), 256>>>(m,   V1, c1, md1, 64, 128);
    conv3k<128,16, 4, 1><<<dim3(1, 1, 64), 256>>>(md1, V2, c2, md2, 64, 64);

    // ---- full convolution with source ----
    fullconv_k<<<dim3(4, 64), 256>>>(md2, source, out);
}